// round 1
// baseline (speedup 1.0000x reference)
#include <cuda_runtime.h>
#include <cuda_bf16.h>
#include <math.h>

#define IMG 224
#define HALF 112
#define OFF 56.0f
#define TL_BASE 38
#define TL_RANGE 18.0f
#define ROWS_PER_BLOCK 8
#define THREADS 256

// sigmoid(10*z) difference mask factor at integer coordinate v for center t, half-length l
__device__ __forceinline__ float mask1d(float v, float t, float l) {
    float z1 = 10.0f * (v - t + l);
    float z2 = 10.0f * (v - t - l);
    float s1 = 1.0f / (1.0f + __expf(-z1));
    float s2 = 1.0f / (1.0f + __expf(-z2));
    return s1 - s2;
}

__global__ __launch_bounds__(THREADS)
void attention_crop_kernel(const float* __restrict__ apn,
                           const float* __restrict__ in,
                           float* __restrict__ out) {
    const int b = blockIdx.y;
    const int tid = threadIdx.x;

    // Per-batch crop params (all threads compute; cheap, avoids extra sync)
    const float a0 = __ldg(&apn[b * 3 + 0]);
    const float a1 = __ldg(&apn[b * 3 + 1]);
    const float a2 = __ldg(&apn[b * 3 + 2]);
    const int tx = HALF + (int)truncf(a0 * OFF + 0.5f);
    const int ty = HALF + (int)truncf(a1 * OFF + 0.5f);
    const int tl = TL_BASE + (int)truncf((a2 + 1.0f) * 0.5f * TL_RANGE);
    const int in_size = 2 * tl;
    const float in_size_f = (float)in_size;
    const float txf = (float)tx, tyf = (float)ty, tlf = (float)tl;

    // Column coefficient tables: absolute col indices + fused (bilinear x mask) weights
    __shared__ int   s_c0[IMG];
    __shared__ int   s_c1[IMG];
    __shared__ float s_a0[IMG];   // (1-wc) * fy(c0)
    __shared__ float s_a1[IMG];   // wc     * fy(c1)

    if (tid < IMG) {
        float src = fmaxf((tid + 0.5f) * in_size_f / 224.0f - 0.5f, 0.0f);
        int   i0  = (int)floorf(src);
        float w   = src - (float)i0;
        int   i1  = min(i0 + 1, in_size - 1);
        int   c0  = (ty - tl) + i0;
        int   c1  = (ty - tl) + i1;
        s_c0[tid] = c0;
        s_c1[tid] = c1;
        s_a0[tid] = (1.0f - w) * mask1d((float)c0, tyf, tlf);
        s_a1[tid] = w          * mask1d((float)c1, tyf, tlf);
    }
    __syncthreads();

    const size_t img_off = (size_t)b * 3 * IMG * IMG;
    const float* inb  = in  + img_off;
    float*       outb = out + img_off;

    const int row_base = blockIdx.x * ROWS_PER_BLOCK;

    #pragma unroll
    for (int rr = 0; rr < ROWS_PER_BLOCK; rr++) {
        const int r = row_base + rr;
        // Row coefficients (scalar per row; every thread computes identically)
        float src = fmaxf((r + 0.5f) * in_size_f / 224.0f - 0.5f, 0.0f);
        int   i0  = (int)floorf(src);
        float wr  = src - (float)i0;
        int   i1  = min(i0 + 1, in_size - 1);
        const int r0a = (tx - tl) + i0;
        const int r1a = (tx - tl) + i1;
        const float wr0 = (1.0f - wr) * mask1d((float)r0a, txf, tlf);
        const float wr1 = wr          * mask1d((float)r1a, txf, tlf);

        // 3 channels x 224 cols = 672 elements for this row
        for (int e = tid; e < 3 * IMG; e += THREADS) {
            const int c = e / IMG;
            const int j = e - c * IMG;

            const float* base = inb + (size_t)c * IMG * IMG;
            const float* row0 = base + (size_t)r0a * IMG;
            const float* row1 = base + (size_t)r1a * IMG;

            const int   c0 = s_c0[j];
            const int   c1 = s_c1[j];
            const float a0c = s_a0[j];
            const float a1c = s_a1[j];

            const float v00 = __ldg(&row0[c0]);
            const float v01 = __ldg(&row0[c1]);
            const float v10 = __ldg(&row1[c0]);
            const float v11 = __ldg(&row1[c1]);

            const float top = fmaf(a0c, v00, a1c * v01);
            const float bot = fmaf(a0c, v10, a1c * v11);
            outb[(size_t)c * IMG * IMG + (size_t)r * IMG + j] = fmaf(wr0, top, wr1 * bot);
        }
    }
}

extern "C" void kernel_launch(void* const* d_in, const int* in_sizes, int n_in,
                              void* d_out, int out_size) {
    const float* apn = (const float*)d_in[0];   // [256, 3]
    const float* in  = (const float*)d_in[1];   // [256, 3, 224, 224]
    float* out = (float*)d_out;                 // [256, 3, 224, 224]

    dim3 grid(IMG / ROWS_PER_BLOCK, 256);       // (28 row-chunks, B)
    attention_crop_kernel<<<grid, THREADS>>>(apn, in, out);
}

// round 3
// speedup vs baseline: 3.6602x; 3.6602x over previous
#include <cuda_runtime.h>
#include <cuda_bf16.h>
#include <math.h>

#define IMG 224
#define HALF 112
#define OFF 56.0f
#define TL_BASE 38
#define TL_RANGE 18.0f
#define RPB 8            // output rows per block
#define THREADS 224      // one thread per output column

// sigmoid(10*z) difference mask factor at coordinate v for center t, half-length l
__device__ __forceinline__ float mask1d(float v, float t, float l) {
    float z1 = 10.0f * (v - t + l);
    float z2 = 10.0f * (v - t - l);
    float s1 = 1.0f / (1.0f + __expf(-z1));
    float s2 = 1.0f / (1.0f + __expf(-z2));
    return s1 - s2;
}

__global__ __launch_bounds__(THREADS)
void attention_crop_kernel(const float* __restrict__ apn,
                           const float* __restrict__ in,
                           float* __restrict__ out) {
    const int b   = blockIdx.y;
    const int tid = threadIdx.x;           // = output column j

    // Per-batch crop params (all threads compute; cheap)
    const float a0p = __ldg(&apn[b * 3 + 0]);
    const float a1p = __ldg(&apn[b * 3 + 1]);
    const float a2p = __ldg(&apn[b * 3 + 2]);
    const int tx = HALF + (int)truncf(a0p * OFF + 0.5f);
    const int ty = HALF + (int)truncf(a1p * OFF + 0.5f);
    const int tl = TL_BASE + (int)truncf((a2p + 1.0f) * 0.5f * TL_RANGE);
    const int in_size = 2 * tl;
    const float scale = (float)in_size * (1.0f / 224.0f);
    const float txf = (float)tx, tyf = (float)ty, tlf = (float)tl;

    // Row coefficient table for this block's RPB rows (threads 0..RPB-1 fill it)
    __shared__ int   s_r0[RPB];
    __shared__ int   s_r1[RPB];
    __shared__ float s_w0[RPB];   // (1-wr) * fx(r0)
    __shared__ float s_w1[RPB];   // wr     * fx(r1)

    const int row_base = blockIdx.x * RPB;
    if (tid < RPB) {
        const int r = row_base + tid;
        float src = fmaxf((r + 0.5f) * scale - 0.5f, 0.0f);
        int   i0  = (int)src;               // src >= 0, floor == trunc
        float wr  = src - (float)i0;
        int   i1  = min(i0 + 1, in_size - 1);
        const int r0a = (tx - tl) + i0;
        const int r1a = (tx - tl) + i1;
        s_r0[tid] = r0a;
        s_r1[tid] = r1a;
        s_w0[tid] = (1.0f - wr) * mask1d((float)r0a, txf, tlf);
        s_w1[tid] = wr          * mask1d((float)r1a, txf, tlf);
    }

    // Column coefficients: fixed per thread, live in registers
    float srcc = fmaxf((tid + 0.5f) * scale - 0.5f, 0.0f);
    int   ci0  = (int)srcc;
    float wc   = srcc - (float)ci0;
    int   ci1  = min(ci0 + 1, in_size - 1);
    const int   c0  = (ty - tl) + ci0;
    const int   c1  = (ty - tl) + ci1;
    const float a0c = (1.0f - wc) * mask1d((float)c0, tyf, tlf);
    const float a1c = wc          * mask1d((float)c1, tyf, tlf);

    __syncthreads();

    // 32-bit indexing from per-batch base pointers
    const float* __restrict__ inb  = in  + (size_t)b * (3 * IMG * IMG);
    float*       __restrict__ outb = out + (size_t)b * (3 * IMG * IMG);

    #pragma unroll
    for (int rr = 0; rr < RPB; rr++) {
        const int   base0 = s_r0[rr] * IMG;
        const int   base1 = s_r1[rr] * IMG;
        const float w0    = s_w0[rr];
        const float w1    = s_w1[rr];
        const int   obase = (row_base + rr) * IMG + tid;

        #pragma unroll
        for (int ch = 0; ch < 3; ch++) {
            const float* __restrict__ p = inb + ch * (IMG * IMG);
            const float v00 = __ldg(p + base0 + c0);
            const float v01 = __ldg(p + base0 + c1);
            const float v10 = __ldg(p + base1 + c0);
            const float v11 = __ldg(p + base1 + c1);
            const float top = fmaf(a0c, v00, a1c * v01);
            const float bot = fmaf(a0c, v10, a1c * v11);
            outb[ch * (IMG * IMG) + obase] = fmaf(w0, top, w1 * bot);
        }
    }
}

extern "C" void kernel_launch(void* const* d_in, const int* in_sizes, int n_in,
                              void* d_out, int out_size) {
    const float* apn = (const float*)d_in[0];   // [256, 3]
    const float* in  = (const float*)d_in[1];   // [256, 3, 224, 224]
    float* out = (float*)d_out;                 // [256, 3, 224, 224]

    dim3 grid(IMG / RPB, 256);                  // (28 row-chunks, B)
    attention_crop_kernel<<<grid, THREADS>>>(apn, in, out);
}